// round 9
// baseline (speedup 1.0000x reference)
#include <cuda_runtime.h>

// ---------------------------------------------------------------------------
// DNN_SKalmanNet_GSS — batch-1 GEMV chain, HBM-bound (~499 MB weights/pass).
// 4 launches, dependency-balanced:
//   KA: l1/l3 GEMV (input built in smem) + gh1/gh2 (Whh@hn)  [~146 MB]
//       (gh depends only on inputs -> fills l1/l3 tails)
//   KB: gi1/gi2 (Wih @ l1/l3)                                [~252 MB]
//   KC: GRU gate fused + W1 GEMV (relu) + bias prewrite      [~67 MB]
//   KD: W2 GEMV split-K x8, atomicAdd into d_out             [~34 MB]
// Inner loop: R1-proven (plain float4 loads, unroll 4, warp-per-row).
// ---------------------------------------------------------------------------

#define H1   5120
#define H2   4096
#define HID  2048
#define IN1  1120

__device__ float g_l1[H1];
__device__ float g_l3[H1];
__device__ float g_gi1[3 * HID];
__device__ float g_gh1[3 * HID];
__device__ float g_gi2[3 * HID];
__device__ float g_gh2[3 * HID];
__device__ float g_hid1[H2];
__device__ float g_hid2[H2];

__device__ __forceinline__ void gemv_core(const float* __restrict__ W,
                                          const float* __restrict__ b,
                                          float* __restrict__ y,
                                          int rows, int c4, int act,
                                          const float4* __restrict__ sx) {
    const int lane = threadIdx.x & 31;
    const int warp = (blockIdx.x * blockDim.x + threadIdx.x) >> 5;
    const int nw   = (gridDim.x * blockDim.x) >> 5;
    for (int row = warp; row < rows; row += nw) {
        const float4* __restrict__ Wr = (const float4*)W + (size_t)row * c4;
        float acc = 0.f;
        #pragma unroll 4
        for (int j = lane; j < c4; j += 32) {
            float4 w = Wr[j];
            float4 x = sx[j];
            acc = fmaf(w.x, x.x, acc);
            acc = fmaf(w.y, x.y, acc);
            acc = fmaf(w.z, x.z, acc);
            acc = fmaf(w.w, x.w, acc);
        }
        #pragma unroll
        for (int o = 16; o; o >>= 1) acc += __shfl_xor_sync(0xffffffffu, acc, o);
        if (lane == 0) {
            float v = acc + b[row];
            if (act) v = fmaxf(v, 0.f);
            y[row] = v;
        }
    }
}

extern __shared__ float4 smem_x[];

// KA: y in [0,4): 0 -> l1 (input built), 1 -> l3 (input built),
//                 2 -> gh1 = Whh1@hn1,   3 -> gh2 = Whh2@hn2.
__global__ void kA(const float* __restrict__ si,
                   const float* __restrict__ oi,
                   const float* __restrict__ ds,
                   const float* __restrict__ dob,
                   const float* __restrict__ le,
                   const float* __restrict__ J,
                   const float* __restrict__ l1W,
                   const float* __restrict__ l1b,
                   const float* __restrict__ l3W,
                   const float* __restrict__ l3b,
                   const float* __restrict__ g1Whh,
                   const float* __restrict__ g1bhh,
                   const float* __restrict__ g2Whh,
                   const float* __restrict__ g2bhh,
                   const float* __restrict__ hn1,
                   const float* __restrict__ hn2) {
    const int seg = blockIdx.y;
    if (seg < 2) {
        const int br = seg;
        float* s = (float*)smem_x;
        for (int i = threadIdx.x; i < IN1; i += blockDim.x) {
            float v;
            if (i < 32)       v = br ? oi[i]       : si[i];
            else if (i < 64)  v = br ? dob[i - 32] : ds[i - 32];
            else if (i < 96)  v = le[i - 64];
            else              v = J[i - 96];
            s[i] = v;
        }
        __syncthreads();
        gemv_core(br ? l3W : l1W, br ? l3b : l1b, br ? g_l3 : g_l1,
                  H1, IN1 / 4, 1, smem_x);
    } else {
        const int br = seg - 2;
        const float* __restrict__ hn = br ? hn2 : hn1;
        const float4* __restrict__ xv = (const float4*)hn;
        for (int j = threadIdx.x; j < HID / 4; j += blockDim.x) smem_x[j] = xv[j];
        __syncthreads();
        gemv_core(br ? g2Whh : g1Whh, br ? g2bhh : g1bhh, br ? g_gh2 : g_gh1,
                  3 * HID, HID / 4, 0, smem_x);
    }
}

// KB: y in [0,2): gi = Wih @ l_out.
__global__ void kB(const float* __restrict__ g1Wih,
                   const float* __restrict__ g1bih,
                   const float* __restrict__ g2Wih,
                   const float* __restrict__ g2bih) {
    const int br = blockIdx.y;
    const float* __restrict__ x = br ? g_l3 : g_l1;
    const float4* __restrict__ xv = (const float4*)x;
    for (int j = threadIdx.x; j < H1 / 4; j += blockDim.x) smem_x[j] = xv[j];
    __syncthreads();
    gemv_core(br ? g2Wih : g1Wih, br ? g2bih : g1bih, br ? g_gi2 : g_gi1,
              3 * HID, H1 / 4, 0, smem_x);
}

// KC: gate fused into staging + hidden = relu(W1@h + b1); block 0 of each
// branch pre-writes output bias b2 into d_out for KD's atomics.
__global__ void kC(const float* __restrict__ hn1,
                   const float* __restrict__ hn2,
                   const float* __restrict__ l2W1,
                   const float* __restrict__ l2b1,
                   const float* __restrict__ l4W1,
                   const float* __restrict__ l4b1,
                   const float* __restrict__ l2b2,
                   const float* __restrict__ l4b2,
                   float* __restrict__ out) {
    const int br = blockIdx.y;
    if (blockIdx.x == 0) {
        const float* b2 = br ? l4b2 : l2b2;
        for (int i = threadIdx.x; i < 1024; i += blockDim.x)
            out[br * 1024 + i] = b2[i];
    }
    const float* __restrict__ gi = br ? g_gi2 : g_gi1;
    const float* __restrict__ gh = br ? g_gh2 : g_gh1;
    const float* __restrict__ hp = br ? hn2 : hn1;
    float* s = (float*)smem_x;
    for (int k = threadIdx.x; k < HID; k += blockDim.x) {
        float r = 1.f / (1.f + __expf(-(gi[k]       + gh[k])));
        float z = 1.f / (1.f + __expf(-(gi[k + HID] + gh[k + HID])));
        float n = tanhf(gi[k + 2 * HID] + r * gh[k + 2 * HID]);
        s[k] = (1.f - z) * n + z * hp[k];
    }
    __syncthreads();
    gemv_core(br ? l4W1 : l2W1, br ? l4b1 : l2b1, br ? g_hid2 : g_hid1,
              H2, HID / 4, 1, smem_x);
}

// KD: split-K x8 output GEMV. y in [0,16): br = y>>3, chunk q = y&7.
// Each block: 8 warps, 8 rows, 512-col partial dot -> atomicAdd into out.
#define CHUNK4 (H2 / 4 / 8)   // 128 float4 per chunk

__global__ void kD(const float* __restrict__ l2W2,
                   const float* __restrict__ l4W2,
                   float* __restrict__ out) {
    const int br = blockIdx.y >> 3;
    const int q  = blockIdx.y & 7;
    const float* __restrict__ W = br ? l4W2 : l2W2;
    const float* __restrict__ x = br ? g_hid2 : g_hid1;

    const float4* __restrict__ xv = (const float4*)x + q * CHUNK4;
    for (int j = threadIdx.x; j < CHUNK4; j += blockDim.x) smem_x[j] = xv[j];
    __syncthreads();

    const int lane = threadIdx.x & 31;
    const int row  = blockIdx.x * 8 + (threadIdx.x >> 5);   // 128 blocks * 8
    const float4* __restrict__ Wr =
        (const float4*)W + (size_t)row * (H2 / 4) + q * CHUNK4;
    float acc = 0.f;
    #pragma unroll 4
    for (int j = lane; j < CHUNK4; j += 32) {
        float4 w  = Wr[j];
        float4 xx = smem_x[j];
        acc = fmaf(w.x, xx.x, acc);
        acc = fmaf(w.y, xx.y, acc);
        acc = fmaf(w.z, xx.z, acc);
        acc = fmaf(w.w, xx.w, acc);
    }
    #pragma unroll
    for (int o = 16; o; o >>= 1) acc += __shfl_xor_sync(0xffffffffu, acc, o);
    if (lane == 0) atomicAdd(&out[br * 1024 + row], acc);
}

extern "C" void kernel_launch(void* const* d_in, const int* in_sizes, int n_in,
                              void* d_out, int out_size) {
    const float* si    = (const float*)d_in[0];
    const float* oi    = (const float*)d_in[1];
    const float* ds    = (const float*)d_in[2];
    const float* dob   = (const float*)d_in[3];
    const float* le    = (const float*)d_in[4];
    const float* J     = (const float*)d_in[5];
    const float* l1W   = (const float*)d_in[6];
    const float* l1b   = (const float*)d_in[7];
    const float* g1Wih = (const float*)d_in[8];
    const float* g1Whh = (const float*)d_in[9];
    const float* g1bih = (const float*)d_in[10];
    const float* g1bhh = (const float*)d_in[11];
    const float* l2W1  = (const float*)d_in[12];
    const float* l2b1  = (const float*)d_in[13];
    const float* l2W2  = (const float*)d_in[14];
    const float* l2b2  = (const float*)d_in[15];
    const float* l3W   = (const float*)d_in[16];
    const float* l3b   = (const float*)d_in[17];
    const float* g2Wih = (const float*)d_in[18];
    const float* g2Whh = (const float*)d_in[19];
    const float* g2bih = (const float*)d_in[20];
    const float* g2bhh = (const float*)d_in[21];
    const float* l4W1  = (const float*)d_in[22];
    const float* l4b1  = (const float*)d_in[23];
    const float* l4W2  = (const float*)d_in[24];
    const float* l4b2  = (const float*)d_in[25];
    const float* hn1   = (const float*)d_in[26];
    const float* hn2   = (const float*)d_in[27];
    float* out = (float*)d_out;

    // KA: grid.x = 768 (covers 6144-row gh segs; 5120-row l1/l3 via row loop)
    //     smem = max(IN1, HID) floats = 8 KB
    kA<<<dim3(768, 4), 256, HID * sizeof(float)>>>(
        si, oi, ds, dob, le, J, l1W, l1b, l3W, l3b,
        g1Whh, g1bhh, g2Whh, g2bhh, hn1, hn2);

    // KB: 6144 rows / 8 warps -> 768 blocks x 2 branches, smem 20 KB
    kB<<<dim3((3 * HID) / 8, 2), 256, H1 * sizeof(float)>>>(
        g1Wih, g1bih, g2Wih, g2bih);

    // KC: 4096 rows / 8 warps -> 512 blocks x 2 branches, smem 8 KB
    kC<<<dim3(H2 / 8, 2), 256, HID * sizeof(float)>>>(
        hn1, hn2, l2W1, l2b1, l4W1, l4b1, l2b2, l4b2, out);

    // KD: 128 blocks x (2 branches * 8 chunks), smem 2 KB
    kD<<<dim3(128, 16), 256, CHUNK4 * sizeof(float4)>>>(l2W2, l4W2, out);

    (void)in_sizes; (void)n_in; (void)out_size;
}